// round 5
// baseline (speedup 1.0000x reference)
#include <cuda_runtime.h>
#include <cstdint>

// Problem constants (match reference)
#define FEAT_W   32
#define FEAT_H   32
#define HW       1024          // 32*32
#define M_GT     64
#define GT_STRIDE 14

// Output tensor offsets in floats. BN = 4096; slab = BN*HW floats.
#define SLAB     4194304ll
#define OFF_CLS   (0ll)
#define OFF_CLSW  (SLAB*1)
#define OFF_R2    (SLAB*2)
#define OFF_R2W   (SLAB*4)
#define OFF_R3    (SLAB*6)
#define OFF_R3W   (SLAB*8)
#define OFF_DL    (SLAB*10)
#define OFF_DLW   (SLAB*11)
#define OFF_DIM   (SLAB*12)
#define OFF_DIMW  (SLAB*15)
#define OFF_ROT   (SLAB*18)
#define OFF_ROTW  (SLAB*19)

// 256-bit streaming store (sm_100a+ PTX v8). 32B-aligned by construction.
__device__ __forceinline__ void stream8(float* p, const float* v) {
    asm volatile("st.global.cs.v8.f32 [%0], {%1,%2,%3,%4,%5,%6,%7,%8};"
                 :: "l"(p), "f"(v[0]), "f"(v[1]), "f"(v[2]), "f"(v[3]),
                    "f"(v[4]), "f"(v[5]), "f"(v[6]), "f"(v[7])
                 : "memory");
}

__global__ __launch_bounds__(128, 8)
void rcnn3d_label_kernel(const float* __restrict__ boxes,
                         const float* __restrict__ gt_boxes,
                         const int*   __restrict__ match_pos_flag,
                         const int*   __restrict__ match_gt_id,
                         float*       __restrict__ out)
{
    const int bn  = blockIdx.x;            // b*N + n
    const int b   = bn >> 10;
    const int tid = threadIdx.x;           // 0..127, one 8-px strip per thread

    __shared__ __align__(16) float exs[FEAT_W];
    __shared__ __align__(16) float eys[FEAT_H];

    // ---- per-box scalars (uniform; broadcast loads) ----
    const float x1 = __ldg(boxes + (size_t)bn * 4 + 0);
    const float y1 = __ldg(boxes + (size_t)bn * 4 + 1);
    const float x2 = __ldg(boxes + (size_t)bn * 4 + 2);
    const float y2 = __ldg(boxes + (size_t)bn * 4 + 3);
    const int gid  = __ldg(match_gt_id + bn);
    const int flag = __ldg(match_pos_flag + bn);

    const float* g = gt_boxes + ((size_t)b * M_GT + gid) * GT_STRIDE;
    const float kxg   = __ldg(g + 4);
    const float kyg   = __ldg(g + 5);
    const float vis   = __ldg(g + 6);
    const float dim0  = __ldg(g + 7);
    const float dim1  = __ldg(g + 8);
    const float dim2  = __ldg(g + 9);
    const float depth = __ldg(g + 12);
    const float rot   = __ldg(g + 13);

    const float cx = 0.5f * (x1 + x2);
    const float cy = 0.5f * (y1 + y2);
    const float hw = 0.5f * (x2 - x1) * 1.2f;   // EXPAND
    const float hh = 0.5f * (y2 - y1) * 1.2f;
    const float ex1 = cx - hw, ex2 = cx + hw;
    const float ey1 = cy - hh, ey2 = cy + hh;
    const float sx = (float)FEAT_W / (ex2 - ex1 + 1.0f);
    const float sy = (float)FEAT_H / (ey2 - ey1 + 1.0f);
    const float kx = (kxg - ex1) * sx;
    const float ky = (kyg - ey1) * sy;
    const bool valid = (vis != 0.0f) && (flag > 0);

    // ---- separable Gaussian tables: 64 expf per CTA ----
    if (tid < FEAT_W) {
        const float d = (float)tid + 0.5f - kx;
        exs[tid] = expf(-(d * d) / 5.12f);       // 2*SIGMA^2
    } else if (tid < FEAT_W + FEAT_H) {
        const int r = tid - FEAT_W;
        const float d = (float)r + 0.5f - ky;
        eys[r] = expf(-(d * d) / 5.12f);
    }
    __syncthreads();

    // ---- analytic 'has': peak of exs[gx]*eys[gy] at clamped-nearest cell ----
    int ixn = __float2int_rn(kx - 0.5f); ixn = min(FEAT_W - 1, max(0, ixn));
    int iyn = __float2int_rn(ky - 0.5f); iyn = min(FEAT_H - 1, max(0, iyn));
    const float smax = exs[ixn] * eys[iyn];
    const bool  has  = valid && (smax >= 0.6f);
    const float hasf = has ? 1.0f : 0.0f;

    // ---- this thread's 8 pixels: row gy, cols gx0..gx0+7 ----
    const int gy  = tid >> 2;              // 32 rows, 4 strips of 8 per row
    const int gx0 = (tid & 3) << 3;
    const float ey   = eys[gy];
    const float offy = ky - (float)gy;
    const float4 e0 = reinterpret_cast<const float4*>(exs)[(tid & 3) * 2];
    const float4 e1 = reinterpret_cast<const float4*>(exs)[(tid & 3) * 2 + 1];
    const float exa[8] = {e0.x, e0.y, e0.z, e0.w, e1.x, e1.y, e1.z, e1.w};

    float m2f[8], m3f[8], t[8];
#pragma unroll
    for (int j = 0; j < 8; ++j) {
        const float sc = exa[j] * ey;
        m2f[j] = (valid && sc >= 0.6f) ? 1.0f : 0.0f;
        m3f[j] = (valid && sc >= 0.5f) ? 1.0f : 0.0f;  // depth thr == 3d thr
    }

    const long long pix  = (long long)tid * 8;
    const long long base = (long long)bn * HW + pix;
    const long long b2c  = (long long)bn * 2 * HW + pix;
    const long long b3c  = (long long)bn * 3 * HW + pix;

    // cls_label
#pragma unroll
    for (int j = 0; j < 8; ++j) t[j] = has ? (exa[j] * ey) : -1.0f;
    stream8(out + OFF_CLS + base, t);
    // cls_label_w
#pragma unroll
    for (int j = 0; j < 8; ++j) t[j] = hasf;
    stream8(out + OFF_CLSW + base, t);

    // reg_2d x / y, weights
#pragma unroll
    for (int j = 0; j < 8; ++j) t[j] = (kx - (float)(gx0 + j)) * m2f[j];
    stream8(out + OFF_R2 + b2c, t);
#pragma unroll
    for (int j = 0; j < 8; ++j) t[j] = offy * m2f[j];
    stream8(out + OFF_R2 + b2c + HW, t);
    stream8(out + OFF_R2W + b2c,      m2f);
    stream8(out + OFF_R2W + b2c + HW, m2f);

    // reg_3d x / y, weights
#pragma unroll
    for (int j = 0; j < 8; ++j) t[j] = (kx - (float)(gx0 + j)) * m3f[j];
    stream8(out + OFF_R3 + b2c, t);
#pragma unroll
    for (int j = 0; j < 8; ++j) t[j] = offy * m3f[j];
    stream8(out + OFF_R3 + b2c + HW, t);
    stream8(out + OFF_R3W + b2c,      m3f);
    stream8(out + OFF_R3W + b2c + HW, m3f);

    // depth
#pragma unroll
    for (int j = 0; j < 8; ++j) t[j] = depth * m3f[j];
    stream8(out + OFF_DL + base, t);
    stream8(out + OFF_DLW + base, m3f);

    // dims (3ch) + weights
#pragma unroll
    for (int j = 0; j < 8; ++j) t[j] = dim0 * m3f[j];
    stream8(out + OFF_DIM + b3c, t);
#pragma unroll
    for (int j = 0; j < 8; ++j) t[j] = dim1 * m3f[j];
    stream8(out + OFF_DIM + b3c + HW, t);
#pragma unroll
    for (int j = 0; j < 8; ++j) t[j] = dim2 * m3f[j];
    stream8(out + OFF_DIM + b3c + 2 * HW, t);
    stream8(out + OFF_DIMW + b3c,          m3f);
    stream8(out + OFF_DIMW + b3c + HW,     m3f);
    stream8(out + OFF_DIMW + b3c + 2 * HW, m3f);

    // rot
#pragma unroll
    for (int j = 0; j < 8; ++j) t[j] = rot * m3f[j];
    stream8(out + OFF_ROT + base, t);
    stream8(out + OFF_ROTW + base, m3f);
}

extern "C" void kernel_launch(void* const* d_in, const int* in_sizes, int n_in,
                              void* d_out, int out_size) {
    const float* boxes          = (const float*)d_in[0];
    const float* gt_boxes       = (const float*)d_in[1];
    const int*   match_pos_flag = (const int*)d_in[2];
    const int*   match_gt_id    = (const int*)d_in[3];
    float* out = (float*)d_out;

    // One CTA per (b,n): 4096 CTAs x 128 threads; each thread writes one
    // 32B-aligned v8 (256-bit) strip of every one of the 20 output channels.
    rcnn3d_label_kernel<<<4096, 128>>>(boxes, gt_boxes, match_pos_flag,
                                       match_gt_id, out);
}